// round 1
// baseline (speedup 1.0000x reference)
#include <cuda_runtime.h>
#include <math.h>

#define BB 8
#define LL 4096
#define DD 1024
#define HH 64
#define HDIM 16
#define MROWS (BB*LL)   // 32768

// ---------------- scratch (device globals; no allocation in kernel_launch) ---
__device__ float g_xn[(size_t)MROWS * DD];
__device__ float g_q [(size_t)MROWS * DD];
__device__ float g_k [(size_t)MROWS * DD];
__device__ float g_v [(size_t)MROWS * DD];
__device__ float g_if[(size_t)MROWS * 2 * HH];
__device__ float g_hs[(size_t)MROWS * DD];
__device__ float g_wif[2 * HH * DD];
__device__ float g_bif[2 * HH];

// ---------------- LayerNorm: one block per row, 256 threads, float4 ----------
__global__ void ln_kernel(const float* __restrict__ x,
                          const float* __restrict__ gamma,
                          const float* __restrict__ beta) {
    __shared__ float s_sum[8], s_sq[8];
    const int row = blockIdx.x;
    const float4* xr = reinterpret_cast<const float4*>(x) + (size_t)row * (DD / 4);
    float4 v = xr[threadIdx.x];
    float s = v.x + v.y + v.z + v.w;
    float q = v.x * v.x + v.y * v.y + v.z * v.z + v.w * v.w;
    #pragma unroll
    for (int o = 16; o; o >>= 1) {
        s += __shfl_xor_sync(0xffffffffu, s, o);
        q += __shfl_xor_sync(0xffffffffu, q, o);
    }
    const int warp = threadIdx.x >> 5, lane = threadIdx.x & 31;
    if (lane == 0) { s_sum[warp] = s; s_sq[warp] = q; }
    __syncthreads();
    if (warp == 0) {
        s = (lane < 8) ? s_sum[lane] : 0.f;
        q = (lane < 8) ? s_sq[lane] : 0.f;
        #pragma unroll
        for (int o = 4; o; o >>= 1) {
            s += __shfl_xor_sync(0xffffffffu, s, o);
            q += __shfl_xor_sync(0xffffffffu, q, o);
        }
        if (lane == 0) { s_sum[0] = s; s_sq[0] = q; }
    }
    __syncthreads();
    const float mean = s_sum[0] * (1.f / DD);
    const float var  = s_sq[0] * (1.f / DD) - mean * mean;
    const float rstd = rsqrtf(var + 1e-5f);
    const float4 gg = reinterpret_cast<const float4*>(gamma)[threadIdx.x];
    const float4 bb = reinterpret_cast<const float4*>(beta)[threadIdx.x];
    float4 o;
    o.x = (v.x - mean) * rstd * gg.x + bb.x;
    o.y = (v.y - mean) * rstd * gg.y + bb.y;
    o.z = (v.z - mean) * rstd * gg.z + bb.z;
    o.w = (v.w - mean) * rstd * gg.w + bb.w;
    reinterpret_cast<float4*>(g_xn)[(size_t)row * (DD / 4) + threadIdx.x] = o;
}

// ---------------- pack i/f weights into one [128,1024] matrix ----------------
__global__ void combine_if_kernel(const float* __restrict__ iw,
                                  const float* __restrict__ ib,
                                  const float* __restrict__ fw,
                                  const float* __restrict__ fb) {
    int idx = blockIdx.x * blockDim.x + threadIdx.x;
    if (idx < 2 * HH * DD) {
        int nrow = idx / DD;
        g_wif[idx] = (nrow < HH) ? iw[idx] : fw[idx - HH * DD];
    }
    if (idx < 2 * HH) g_bif[idx] = (idx < HH) ? ib[idx] : fb[idx - HH];
}

// ---------------- SGEMM: out[m,n] = scale*(sum_k A[m,k]*W[n,k] + bias[n]) (+resid)
// BM=BN=128, BK=16, 256 threads, 8x8 microtile
template <bool RESID>
__global__ __launch_bounds__(256) void sgemm_kernel(
    const float* __restrict__ A,     // [M,K]
    const float* __restrict__ W,     // [N,K] row-major
    const float* __restrict__ bias,  // [N]
    const float* __restrict__ resid, // [M,N] or null
    float* __restrict__ out,         // [M,N]
    int K, int N, float scale) {
    __shared__ float As[16][128];
    __shared__ float Bs[16][128];
    const int tid = threadIdx.x;
    const int bm = blockIdx.y * 128;
    const int bn = blockIdx.x * 128;
    const int tx = tid & 15, ty = tid >> 4;
    float acc[8][8];
    #pragma unroll
    for (int i = 0; i < 8; ++i)
        #pragma unroll
        for (int j = 0; j < 8; ++j) acc[i][j] = 0.f;

    const int lr = tid >> 2;        // 0..63
    const int lk = (tid & 3) * 4;   // 0,4,8,12
    const float* Ap  = A + (size_t)(bm + lr) * K + lk;
    const float* Ap2 = Ap + (size_t)64 * K;
    const float* Wp  = W + (size_t)(bn + lr) * K + lk;
    const float* Wp2 = Wp + (size_t)64 * K;

    for (int k0 = 0; k0 < K; k0 += 16) {
        float4 a0 = *(const float4*)(Ap  + k0);
        float4 a1 = *(const float4*)(Ap2 + k0);
        float4 b0 = *(const float4*)(Wp  + k0);
        float4 b1 = *(const float4*)(Wp2 + k0);
        __syncthreads();
        As[lk + 0][lr] = a0.x; As[lk + 1][lr] = a0.y;
        As[lk + 2][lr] = a0.z; As[lk + 3][lr] = a0.w;
        As[lk + 0][lr + 64] = a1.x; As[lk + 1][lr + 64] = a1.y;
        As[lk + 2][lr + 64] = a1.z; As[lk + 3][lr + 64] = a1.w;
        Bs[lk + 0][lr] = b0.x; Bs[lk + 1][lr] = b0.y;
        Bs[lk + 2][lr] = b0.z; Bs[lk + 3][lr] = b0.w;
        Bs[lk + 0][lr + 64] = b1.x; Bs[lk + 1][lr + 64] = b1.y;
        Bs[lk + 2][lr + 64] = b1.z; Bs[lk + 3][lr + 64] = b1.w;
        __syncthreads();
        #pragma unroll
        for (int kk = 0; kk < 16; ++kk) {
            float4 aA = *(const float4*)&As[kk][ty * 8];
            float4 aB = *(const float4*)&As[kk][ty * 8 + 4];
            float4 bA = *(const float4*)&Bs[kk][tx * 8];
            float4 bB = *(const float4*)&Bs[kk][tx * 8 + 4];
            float a[8] = {aA.x, aA.y, aA.z, aA.w, aB.x, aB.y, aB.z, aB.w};
            float b[8] = {bA.x, bA.y, bA.z, bA.w, bB.x, bB.y, bB.z, bB.w};
            #pragma unroll
            for (int i = 0; i < 8; ++i)
                #pragma unroll
                for (int j = 0; j < 8; ++j)
                    acc[i][j] = fmaf(a[i], b[j], acc[i][j]);
        }
    }
    // epilogue
    #pragma unroll
    for (int i = 0; i < 8; ++i) {
        const size_t row = (size_t)(bm + ty * 8 + i);
        #pragma unroll
        for (int j = 0; j < 8; j += 4) {
            const int col = bn + tx * 8 + j;
            float4 bs = *(const float4*)(bias + col);
            float4 o;
            o.x = scale * (acc[i][j + 0] + bs.x);
            o.y = scale * (acc[i][j + 1] + bs.y);
            o.z = scale * (acc[i][j + 2] + bs.z);
            o.w = scale * (acc[i][j + 3] + bs.w);
            if (RESID) {
                float4 r = *(const float4*)(resid + row * N + col);
                o.x += r.x; o.y += r.y; o.z += r.z; o.w += r.w;
            }
            *(float4*)(out + row * N + col) = o;
        }
    }
}

// ---------------- mLSTM scan: 16 lanes per (b,h) chain, 2 chains per warp ----
__global__ void scan_kernel() {
    const int warpId = blockIdx.x;          // 0..255
    const int lane = threadIdx.x;           // 0..31
    const int sub = lane >> 4;
    const int e = lane & 15;
    const int chain = warpId * 2 + sub;     // 0..511
    const int b = chain >> 6;
    const int h = chain & 63;

    const size_t baseQ = (size_t)b * LL * DD + h * HDIM + e;
    const size_t baseIF = (size_t)b * LL * (2 * HH);

    float C[16];
    #pragma unroll
    for (int d = 0; d < 16; ++d) C[d] = 0.f;
    float n = 0.f, m = 0.f;

    size_t off = baseQ;
    size_t offIF = baseIF;
    float qe = g_q[off], ke = g_k[off], ve = g_v[off];
    float it = g_if[offIF + h];
    float ft = g_if[offIF + HH + h];

    for (int t = 0; t < LL; ++t) {
        const size_t off2 = off + DD;
        const size_t offIF2 = offIF + 2 * HH;
        // prefetch next step (independent of state -> hides DRAM latency)
        float qn = qe, kn = ke, vn = ve, in_ = it, fn = ft;
        if (t + 1 < LL) {
            qn = g_q[off2]; kn = g_k[off2]; vn = g_v[off2];
            in_ = g_if[offIF2 + h]; fn = g_if[offIF2 + HH + h];
        }

        const float m_new = fmaxf(ft + m, it);
        const float fd = __expf(ft + m - m_new);
        const float id = __expf(it - m_new);
        m = m_new;
        const float kid = id * ke;       // i * k[e]
        n = fd * n + kid;                // n_new[e]

        float cq = 0.f;
        #pragma unroll
        for (int d = 0; d < 16; ++d) {
            const float vd = __shfl_sync(0xffffffffu, ve, d, 16);
            const float qd = __shfl_sync(0xffffffffu, qe, d, 16);
            C[d] = fd * C[d] + vd * kid; // C_new[d][e]
            cq = fmaf(C[d], qd, cq);     // sum_d C[d][e]*q[d]
        }

        float nq = n * qe;
        #pragma unroll
        for (int o = 8; o; o >>= 1) nq += __shfl_xor_sync(0xffffffffu, nq, o, 16);
        const float denom = fmaxf(fabsf(nq), 1.0f);

        g_hs[off] = cq / denom;

        off = off2; offIF = offIF2;
        qe = qn; ke = kn; ve = vn; it = in_; ft = fn;
    }
}

// ---------------- launch --------------------------------------------------
extern "C" void kernel_launch(void* const* d_in, const int* in_sizes, int n_in,
                              void* d_out, int out_size) {
    (void)in_sizes; (void)n_in; (void)out_size;
    const float* x     = (const float*)d_in[0];
    const float* gamma = (const float*)d_in[1];
    const float* beta  = (const float*)d_in[2];
    const float* qw    = (const float*)d_in[3];
    const float* qb    = (const float*)d_in[4];
    const float* kw    = (const float*)d_in[5];
    const float* kb    = (const float*)d_in[6];
    const float* vw    = (const float*)d_in[7];
    const float* vb    = (const float*)d_in[8];
    const float* ow    = (const float*)d_in[9];
    const float* ob    = (const float*)d_in[10];
    const float* iw    = (const float*)d_in[11];
    const float* ib    = (const float*)d_in[12];
    const float* fw    = (const float*)d_in[13];
    const float* fb    = (const float*)d_in[14];
    float* out = (float*)d_out;

    float *xn, *qp, *kp, *vp, *ifp, *hs, *wif, *bif;
    cudaGetSymbolAddress((void**)&xn,  g_xn);
    cudaGetSymbolAddress((void**)&qp,  g_q);
    cudaGetSymbolAddress((void**)&kp,  g_k);
    cudaGetSymbolAddress((void**)&vp,  g_v);
    cudaGetSymbolAddress((void**)&ifp, g_if);
    cudaGetSymbolAddress((void**)&hs,  g_hs);
    cudaGetSymbolAddress((void**)&wif, g_wif);
    cudaGetSymbolAddress((void**)&bif, g_bif);

    ln_kernel<<<MROWS, 256>>>(x, gamma, beta);
    combine_if_kernel<<<(2 * HH * DD + 255) / 256, 256>>>(iw, ib, fw, fb);

    dim3 gridBig(DD / 128, MROWS / 128);   // (8, 256)
    dim3 gridIF(1, MROWS / 128);           // (1, 256)
    sgemm_kernel<false><<<gridBig, 256>>>(xn, qw, qb, nullptr, qp, DD, DD, 1.0f);
    sgemm_kernel<false><<<gridBig, 256>>>(xn, kw, kb, nullptr, kp, DD, DD, 0.25f);
    sgemm_kernel<false><<<gridBig, 256>>>(xn, vw, vb, nullptr, vp, DD, DD, 1.0f);
    sgemm_kernel<false><<<gridIF, 256>>>(xn, wif, bif, nullptr, ifp, DD, 2 * HH, 1.0f);

    scan_kernel<<<256, 32>>>();

    sgemm_kernel<true><<<gridBig, 256>>>(hs, ow, ob, x, out, DD, DD, 1.0f);
}

// round 4
// speedup vs baseline: 2.0819x; 2.0819x over previous
#include <cuda_runtime.h>
#include <cuda_bf16.h>
#include <cstdint>
#include <math.h>

#define BB 8
#define LL 4096
#define DD 1024
#define HH 64
#define HDIM 16
#define MROWS (BB*LL)        // 32768
#define KSPLIT 3072          // [hi | hi | lo] * 1024
#define KBYTES (KSPLIT*2)    // 6144 bytes per row
#define BKELEM 64            // bf16 elems per k-chunk (=128 bytes)
#define NCHUNKS (KSPLIT/BKELEM)  // 48

#if defined(__CUDA_ARCH__) && (__CUDA_ARCH__ == 1030) && defined(__CUDA_ARCH_FEAT_SM103_ALL)
#define HAS_TCGEN05 1
#else
#define HAS_TCGEN05 0
#endif

// ---------------- device scratch ------------------------------------------
__device__ __nv_bfloat16 g_a2[(size_t)MROWS * KSPLIT];   // split xn
__device__ __nv_bfloat16 g_h2[(size_t)MROWS * KSPLIT];   // split hs
__device__ float g_q [(size_t)MROWS * DD];
__device__ float g_k [(size_t)MROWS * DD];
__device__ float g_v [(size_t)MROWS * DD];
__device__ float g_if[(size_t)MROWS * 2 * HH];
__device__ __nv_bfloat16 g_qw2[(size_t)DD * KSPLIT];
__device__ __nv_bfloat16 g_kw2[(size_t)DD * KSPLIT];
__device__ __nv_bfloat16 g_vw2[(size_t)DD * KSPLIT];
__device__ __nv_bfloat16 g_ow2[(size_t)DD * KSPLIT];
__device__ __nv_bfloat16 g_wif2[(size_t)(2*HH) * KSPLIT];
__device__ float g_wif[2 * HH * DD];
__device__ float g_bif[2 * HH];

// ---------------- PTX helpers (sm_103a only) -------------------------------
__device__ __forceinline__ uint32_t smem_u32(const void* p) {
    uint32_t a;
    asm("{ .reg .u64 t; cvta.to.shared.u64 t, %1; cvt.u32.u64 %0, t; }"
        : "=r"(a) : "l"(p));
    return a;
}

#if HAS_TCGEN05
__device__ __forceinline__ uint32_t elect_one_pred() {
    uint32_t pred;
    asm volatile("{\n\t.reg .pred p;\n\telect.sync _|p, 0xFFFFFFFF;\n\t"
                 "selp.b32 %0, 1, 0, p;\n\t}" : "=r"(pred));
    return pred;
}
#define TCGEN05_ALLOC(saddr, n) \
    asm volatile("tcgen05.alloc.cta_group::1.sync.aligned.shared::cta.b32 [%0], %1;" \
                 :: "r"((uint32_t)(saddr)), "r"((uint32_t)(n)) : "memory")
#define TCGEN05_DEALLOC(taddr, n) \
    asm volatile("tcgen05.dealloc.cta_group::1.sync.aligned.b32 %0, %1;" \
                 :: "r"(taddr), "r"((uint32_t)(n)))
#define TCGEN05_RELINQ() \
    asm volatile("tcgen05.relinquish_alloc_permit.cta_group::1.sync.aligned;")
#define TCGEN05_COMMIT(mbar) \
    asm volatile("tcgen05.commit.cta_group::1.mbarrier::arrive::one.shared::cluster.b64 [%0];" \
                 :: "r"((uint32_t)(mbar)) : "memory")
#define TCGEN05_FENCE_AFTER() \
    asm volatile("tcgen05.fence::after_thread_sync;" ::: "memory")
#define TCGEN05_FENCE_BEFORE() \
    asm volatile("tcgen05.fence::before_thread_sync;" ::: "memory")
#define TCGEN05_WAIT_LD() \
    asm volatile("tcgen05.wait::ld.sync.aligned;" ::: "memory")
#define FENCE_PROXY_ASYNC() \
    asm volatile("fence.proxy.async.shared::cta;" ::: "memory")
#define MBARRIER_INIT(mbar, cnt) \
    asm volatile("mbarrier.init.shared.b64 [%0], %1;" \
                 :: "r"((uint32_t)(mbar)), "r"((uint32_t)(cnt)) : "memory")
__device__ __forceinline__ void mbar_inval(uint32_t a) {
    asm volatile("mbarrier.inval.shared.b64 [%0];" :: "r"(a) : "memory");
}
#define MBARRIER_WAIT_PARITY(mbar, par) do { \
    uint32_t _m = (uint32_t)(mbar); uint32_t _p = (uint32_t)(par); uint32_t _d; \
    asm volatile("{\n\t.reg .pred p;\n\t" \
        "mbarrier.try_wait.parity.acquire.cta.shared::cta.b64 p, [%1], %2;\n\t" \
        "selp.b32 %0, 1, 0, p;\n\t}" : "=r"(_d) : "r"(_m), "r"(_p) : "memory"); \
    if (!_d) { \
        asm volatile("{\n\t.reg .pred P1;\n\t" \
            "WL_%=:\n\t" \
            "mbarrier.try_wait.parity.acquire.cta.shared::cta.b64 P1, [%0], %1, 0x989680;\n\t" \
            "@P1 bra.uni WD_%=;\n\tbra.uni WL_%=;\n\tWD_%=:\n\t}" \
            :: "r"(_m), "r"(_p) : "memory"); \
    } \
} while (0)
// SS-form bf16 MMA, cta_group::1
#define TCGEN05_MMA_F16_SS(dtm, adesc, bdesc, idesc, en) do { \
    uint32_t _e = (en) ? 1u : 0u; \
    asm volatile("{\n\t.reg .pred p;\n\tsetp.ne.u32 p, %5, 0;\n\t" \
        "tcgen05.mma.cta_group::1.kind::f16 [%0], %1, %2, %3, {%4, %4, %4, %4}, p;\n\t}" \
        :: "r"(dtm), "l"(adesc), "l"(bdesc), "r"(idesc), "r"(0u), "r"(_e) : "memory"); \
} while (0)
#define TCGEN05_LD_X32(r, taddr) \
    asm volatile("tcgen05.ld.sync.aligned.32x32b.x32.b32 " \
        "{%0, %1, %2, %3, %4, %5, %6, %7, %8, %9, %10, %11, %12, %13, %14, %15, " \
        "%16, %17, %18, %19, %20, %21, %22, %23, %24, %25, %26, %27, %28, %29, %30, %31}, [%32];" \
        : "=r"((r)[0]),  "=r"((r)[1]),  "=r"((r)[2]),  "=r"((r)[3]), \
          "=r"((r)[4]),  "=r"((r)[5]),  "=r"((r)[6]),  "=r"((r)[7]), \
          "=r"((r)[8]),  "=r"((r)[9]),  "=r"((r)[10]), "=r"((r)[11]), \
          "=r"((r)[12]), "=r"((r)[13]), "=r"((r)[14]), "=r"((r)[15]), \
          "=r"((r)[16]), "=r"((r)[17]), "=r"((r)[18]), "=r"((r)[19]), \
          "=r"((r)[20]), "=r"((r)[21]), "=r"((r)[22]), "=r"((r)[23]), \
          "=r"((r)[24]), "=r"((r)[25]), "=r"((r)[26]), "=r"((r)[27]), \
          "=r"((r)[28]), "=r"((r)[29]), "=r"((r)[30]), "=r"((r)[31]) \
        : "r"(taddr))

static constexpr uint64_t SMEM_DESC_BASE_SW128 =
    (uint64_t(2)  << 61) | (uint64_t(1) << 46) | (uint64_t(64) << 32) | (uint64_t(1) << 16);
#define MAKE_SMEM_DESC(a) (SMEM_DESC_BASE_SW128 | ((uint64_t)((a) >> 4) & 0x3FFF))

// idesc: f32 accum, bf16 A/B, M=128, N=128
static constexpr uint32_t MMA_IDESC =
    (1u << 4) | (1u << 7) | (1u << 10) | ((128u / 8) << 17) | ((128u / 16) << 24);
#endif  // HAS_TCGEN05

#define SWZ128(off) ((off) ^ (((off) >> 3) & 0x70))

// ---------------- bf16 split helper ----------------------------------------
__device__ __forceinline__ void split2(float v, __nv_bfloat16& hi, __nv_bfloat16& lo) {
    hi = __float2bfloat16(v);
    lo = __float2bfloat16(v - __bfloat162float(hi));
}

// ---------------- LayerNorm fused with bf16 split output --------------------
__global__ void ln_split_kernel(const float* __restrict__ x,
                                const float* __restrict__ gamma,
                                const float* __restrict__ beta) {
    __shared__ float s_sum[8], s_sq[8];
    const int row = blockIdx.x;
    const float4* xr = reinterpret_cast<const float4*>(x) + (size_t)row * (DD / 4);
    float4 v = xr[threadIdx.x];
    float s = v.x + v.y + v.z + v.w;
    float q = v.x * v.x + v.y * v.y + v.z * v.z + v.w * v.w;
    #pragma unroll
    for (int o = 16; o; o >>= 1) {
        s += __shfl_xor_sync(0xffffffffu, s, o);
        q += __shfl_xor_sync(0xffffffffu, q, o);
    }
    const int warp = threadIdx.x >> 5, lane = threadIdx.x & 31;
    if (lane == 0) { s_sum[warp] = s; s_sq[warp] = q; }
    __syncthreads();
    if (warp == 0) {
        s = (lane < 8) ? s_sum[lane] : 0.f;
        q = (lane < 8) ? s_sq[lane] : 0.f;
        #pragma unroll
        for (int o = 4; o; o >>= 1) {
            s += __shfl_xor_sync(0xffffffffu, s, o);
            q += __shfl_xor_sync(0xffffffffu, q, o);
        }
        if (lane == 0) { s_sum[0] = s; s_sq[0] = q; }
    }
    __syncthreads();
    const float mean = s_sum[0] * (1.f / DD);
    const float var  = s_sq[0] * (1.f / DD) - mean * mean;
    const float rstd = rsqrtf(var + 1e-5f);
    const float4 gg = reinterpret_cast<const float4*>(gamma)[threadIdx.x];
    const float4 bb = reinterpret_cast<const float4*>(beta)[threadIdx.x];
    float o0 = (v.x - mean) * rstd * gg.x + bb.x;
    float o1 = (v.y - mean) * rstd * gg.y + bb.y;
    float o2 = (v.z - mean) * rstd * gg.z + bb.z;
    float o3 = (v.w - mean) * rstd * gg.w + bb.w;
    __nv_bfloat16 h0, h1, h2, h3, l0, l1, l2, l3;
    split2(o0, h0, l0); split2(o1, h1, l1); split2(o2, h2, l2); split2(o3, h3, l3);
    __nv_bfloat16* dst = g_a2 + (size_t)row * KSPLIT + threadIdx.x * 4;
    __nv_bfloat162* d0 = reinterpret_cast<__nv_bfloat162*>(dst);
    __nv_bfloat162* d1 = reinterpret_cast<__nv_bfloat162*>(dst + 1024);
    __nv_bfloat162* d2 = reinterpret_cast<__nv_bfloat162*>(dst + 2048);
    __nv_bfloat162 hA(h0, h1), hB(h2, h3), lA(l0, l1), lB(l2, l3);
    d0[0] = hA; d0[1] = hB;
    d1[0] = hA; d1[1] = hB;
    d2[0] = lA; d2[1] = lB;
}

// ---------------- generic fp32 -> split-bf16 [rows,3072] (B-side) -----------
__global__ void split_kernel(const float* __restrict__ src, __nv_bfloat16* __restrict__ dst,
                             int rows) {
    int i = blockIdx.x * blockDim.x + threadIdx.x;   // group of 4 elems
    if (i >= rows * 256) return;
    int row = i >> 8;
    int g = i & 255;
    float4 v = reinterpret_cast<const float4*>(src + (size_t)row * DD)[g];
    __nv_bfloat16 h0, h1, h2, h3, l0, l1, l2, l3;
    split2(v.x, h0, l0); split2(v.y, h1, l1); split2(v.z, h2, l2); split2(v.w, h3, l3);
    __nv_bfloat16* d = dst + (size_t)row * KSPLIT + g * 4;
    __nv_bfloat162 hA(h0, h1), hB(h2, h3), lA(l0, l1), lB(l2, l3);
    reinterpret_cast<__nv_bfloat162*>(d)[0] = hA;
    reinterpret_cast<__nv_bfloat162*>(d)[1] = hB;
    reinterpret_cast<__nv_bfloat162*>(d + 1024)[0] = lA;   // B-side order: [hi | lo | hi]
    reinterpret_cast<__nv_bfloat162*>(d + 1024)[1] = lB;
    reinterpret_cast<__nv_bfloat162*>(d + 2048)[0] = hA;
    reinterpret_cast<__nv_bfloat162*>(d + 2048)[1] = hB;
}

// ---------------- pack i/f weights -----------------------------------------
__global__ void combine_if_kernel(const float* __restrict__ iw,
                                  const float* __restrict__ ib,
                                  const float* __restrict__ fw,
                                  const float* __restrict__ fb) {
    int idx = blockIdx.x * blockDim.x + threadIdx.x;
    if (idx < 2 * HH * DD) {
        int nrow = idx / DD;
        g_wif[idx] = (nrow < HH) ? iw[idx] : fw[idx - HH * DD];
    }
    if (idx < 2 * HH) g_bif[idx] = (idx < HH) ? ib[idx] : fb[idx - HH];
}

// ---------------- tcgen05 GEMM: out[m,n]=scale*(A2@B2^T + bias) (+resid) ----
// A2: [M, 3072] bf16 (hi|hi|lo), B2: [N, 3072] bf16 (hi|lo|hi)
template <bool RESID>
__global__ void __launch_bounds__(256, 2) mma_gemm_kernel(
    const __nv_bfloat16* __restrict__ A2,
    const __nv_bfloat16* __restrict__ B2,
    const float* __restrict__ bias,
    const float* __restrict__ resid,
    float* __restrict__ out,
    int N, float scale)
{
#if HAS_TCGEN05
    extern __shared__ char smem_raw[];
    char* smem = (char*)(((uintptr_t)smem_raw + 1023) & ~(uintptr_t)1023);
    __shared__ __align__(16) uint64_t s_mbar[2];
    __shared__ uint32_t s_tmem;

    const int tid = threadIdx.x;
    const int wid = tid >> 5;
    const int bm = blockIdx.y * 128;
    const int bn = blockIdx.x * 128;
    const uint32_t smem_base = smem_u32(smem);

    if (wid == 0) {
        TCGEN05_ALLOC(smem_u32(&s_tmem), 128);
        TCGEN05_RELINQ();
    }
    if (tid == 0) {
        MBARRIER_INIT(smem_u32(&s_mbar[0]), 1);
        MBARRIER_INIT(smem_u32(&s_mbar[1]), 1);
    }
    __syncthreads();
    const uint32_t tmem_d = s_tmem;
    const uint32_t mbar0 = smem_u32(&s_mbar[0]);
    const uint32_t mbar1 = smem_u32(&s_mbar[1]);

    const char* Abase = (const char*)(A2 + (size_t)bm * KSPLIT);
    const char* Bbase = (const char*)(B2 + (size_t)bn * KSPLIT);

    auto load_chunk = [&](int kc, int s) {
        const char* ag = Abase + (size_t)kc * 128;
        const char* bg = Bbase + (size_t)kc * 128;
        char* sa = smem + s * 32768;
        char* sb = sa + 16384;
        #pragma unroll
        for (int i = 0; i < 4; ++i) {
            int cidx = tid + i * 256;
            int row = cidx >> 3;
            int c16 = cidx & 7;
            uint4 va = *(const uint4*)(ag + (size_t)row * KBYTES + c16 * 16);
            uint4 vb = *(const uint4*)(bg + (size_t)row * KBYTES + c16 * 16);
            uint32_t off = row * 128 + c16 * 16;
            uint32_t sw = SWZ128(off);
            *(uint4*)(sa + sw) = va;
            *(uint4*)(sb + sw) = vb;
        }
    };

    load_chunk(0, 0);
    __syncthreads();

    int phase0 = 0, phase1 = 0;
    for (int kc = 0; kc < NCHUNKS; ++kc) {
        const int s = kc & 1;
        if (wid == 0) {
            FENCE_PROXY_ASYNC();
            if (elect_one_pred()) {
                uint64_t ad = MAKE_SMEM_DESC(smem_base + s * 32768);
                uint64_t bd = MAKE_SMEM_DESC(smem_base + s * 32768 + 16384);
                #pragma unroll
                for (int j = 0; j < 4; ++j)
                    TCGEN05_MMA_F16_SS(tmem_d, ad + j * 2, bd + j * 2, MMA_IDESC,
                                       (kc > 0) || (j > 0));
                TCGEN05_COMMIT(s == 0 ? mbar0 : mbar1);
            }
        }
        if (kc + 1 < NCHUNKS) {
            const int s2 = (kc + 1) & 1;
            if (kc >= 1) {
                if (s2 == 0) { MBARRIER_WAIT_PARITY(mbar0, phase0); phase0 ^= 1; }
                else         { MBARRIER_WAIT_PARITY(mbar1, phase1); phase1 ^= 1; }
            }
            load_chunk(kc + 1, s2);
        }
        __syncthreads();
    }
    // last chunk committed to mbar1
    MBARRIER_WAIT_PARITY(mbar1, phase1);
    TCGEN05_FENCE_AFTER();

    // epilogue: warps 0-3 -> cols 0..63, warps 4-7 -> cols 64..127
    const int colbase = (wid >> 2) * 64;
    const int row = bm + (wid & 3) * 32 + (tid & 31);
    #pragma unroll
    for (int cb = 0; cb < 64; cb += 32) {
        uint32_t dr[32];
        TCGEN05_LD_X32(dr, tmem_d + colbase + cb);
        TCGEN05_WAIT_LD();
        TCGEN05_FENCE_BEFORE();
        #pragma unroll
        for (int c = 0; c < 32; c += 4) {
            const int col = bn + colbase + cb + c;
            float4 bs = *(const float4*)(bias + col);
            float4 o;
            o.x = scale * (__uint_as_float(dr[c + 0]) + bs.x);
            o.y = scale * (__uint_as_float(dr[c + 1]) + bs.y);
            o.z = scale * (__uint_as_float(dr[c + 2]) + bs.z);
            o.w = scale * (__uint_as_float(dr[c + 3]) + bs.w);
            if (RESID) {
                float4 r = *(const float4*)(resid + (size_t)row * N + col);
                o.x += r.x; o.y += r.y; o.z += r.z; o.w += r.w;
            }
            *(float4*)(out + (size_t)row * N + col) = o;
        }
    }
    __syncthreads();
    if (tid == 0) { mbar_inval(mbar0); mbar_inval(mbar1); }
    __syncthreads();
    if (wid == 0) TCGEN05_DEALLOC(tmem_d, 128);
#else
    // Fallback for the compute_103 PTX pass (never selected on sm_103a HW,
    // which loads the sm_103a cubin; kept correct in case of PTX JIT).
    const int tid = threadIdx.x;
    const int bm = blockIdx.y * 128;
    const int bn = blockIdx.x * 128;
    // 256 threads; each computes 64 outputs (8 rows x 8 cols)
    const int r0 = (tid >> 4) * 8;   // 0..120
    const int c0 = (tid & 15) * 8;   // 0..120
    for (int i = 0; i < 8; ++i) {
        const int row = bm + r0 + i;
        const __nv_bfloat16* ar = A2 + (size_t)row * KSPLIT;
        for (int j = 0; j < 8; ++j) {
            const int col = bn + c0 + j;
            const __nv_bfloat16* br = B2 + (size_t)col * KSPLIT;
            float acc = 0.f;
            for (int k = 0; k < KSPLIT; ++k)
                acc += __bfloat162float(ar[k]) * __bfloat162float(br[k]);
            float o = scale * (acc + bias[col]);
            if (RESID) o += resid[(size_t)row * N + col];
            out[(size_t)row * N + col] = o;
        }
    }
#endif
}

// ---------------- mLSTM scan: writes split-bf16 hs directly -----------------
__global__ void scan_kernel() {
    const int warpId = blockIdx.x;          // 0..255
    const int lane = threadIdx.x;           // 0..31
    const int sub = lane >> 4;
    const int e = lane & 15;
    const int chain = warpId * 2 + sub;     // 0..511
    const int b = chain >> 6;
    const int h = chain & 63;

    const size_t baseQ = (size_t)b * LL * DD + h * HDIM + e;
    const size_t baseIF = (size_t)b * LL * (2 * HH);
    size_t h2off = (size_t)b * LL * KSPLIT + h * HDIM + e;

    float C[16];
    #pragma unroll
    for (int d = 0; d < 16; ++d) C[d] = 0.f;
    float n = 0.f, m = 0.f;

    size_t off = baseQ;
    size_t offIF = baseIF;
    float qe = g_q[off], ke = g_k[off], ve = g_v[off];
    float it = g_if[offIF + h];
    float ft = g_if[offIF + HH + h];

    for (int t = 0; t < LL; ++t) {
        const size_t off2 = off + DD;
        const size_t offIF2 = offIF + 2 * HH;
        float qn = qe, kn = ke, vn = ve, in_ = it, fn = ft;
        if (t + 1 < LL) {
            qn = g_q[off2]; kn = g_k[off2]; vn = g_v[off2];
            in_ = g_if[offIF2 + h]; fn = g_if[offIF2 + HH + h];
        }

        const float m_new = fmaxf(ft + m, it);
        const float fd = __expf(ft + m - m_new);
        const float id = __expf(it - m_new);
        m = m_new;
        const float kid = id * ke;
        n = fd * n + kid;

        float cq = 0.f;
        #pragma unroll
        for (int d = 0; d < 16; ++d) {
            const float vd = __shfl_sync(0xffffffffu, ve, d, 16);
            const float qd = __shfl_sync(0xffffffffu, qe, d, 16);
            C[d] = fd * C[d] + vd * kid;
            cq = fmaf(C[d], qd, cq);
        }

        float nq = n * qe;
        #pragma unroll
        for (int o = 8; o; o >>= 1) nq += __shfl_xor_sync(0xffffffffu, nq, o, 16);
        const float denom = fmaxf(fabsf(nq), 1.0f);

        const float hval = cq / denom;
        __nv_bfloat16 hh, hl;
        split2(hval, hh, hl);
        g_h2[h2off] = hh;
        g_h2[h2off + 1024] = hh;
        g_h2[h2off + 2048] = hl;

        off = off2; offIF = offIF2; h2off += KSPLIT;
        qe = qn; ke = kn; ve = vn; it = in_; ft = fn;
    }
}

// ---------------- launch ----------------------------------------------------
extern "C" void kernel_launch(void* const* d_in, const int* in_sizes, int n_in,
                              void* d_out, int out_size) {
    (void)in_sizes; (void)n_in; (void)out_size;
    const float* x     = (const float*)d_in[0];
    const float* gamma = (const float*)d_in[1];
    const float* beta  = (const float*)d_in[2];
    const float* qw    = (const float*)d_in[3];
    const float* qb    = (const float*)d_in[4];
    const float* kw    = (const float*)d_in[5];
    const float* kb    = (const float*)d_in[6];
    const float* vw    = (const float*)d_in[7];
    const float* vb    = (const float*)d_in[8];
    const float* ow    = (const float*)d_in[9];
    const float* ob    = (const float*)d_in[10];
    const float* iw    = (const float*)d_in[11];
    const float* ib    = (const float*)d_in[12];
    const float* fw    = (const float*)d_in[13];
    const float* fb    = (const float*)d_in[14];
    float* out = (float*)d_out;

    __nv_bfloat16 *a2, *h2, *qw2, *kw2, *vw2, *ow2, *wif2;
    float *qp, *kp, *vp, *ifp, *wif, *bif;
    cudaGetSymbolAddress((void**)&a2,   g_a2);
    cudaGetSymbolAddress((void**)&h2,   g_h2);
    cudaGetSymbolAddress((void**)&qw2,  g_qw2);
    cudaGetSymbolAddress((void**)&kw2,  g_kw2);
    cudaGetSymbolAddress((void**)&vw2,  g_vw2);
    cudaGetSymbolAddress((void**)&ow2,  g_ow2);
    cudaGetSymbolAddress((void**)&wif2, g_wif2);
    cudaGetSymbolAddress((void**)&qp,   g_q);
    cudaGetSymbolAddress((void**)&kp,   g_k);
    cudaGetSymbolAddress((void**)&vp,   g_v);
    cudaGetSymbolAddress((void**)&ifp,  g_if);
    cudaGetSymbolAddress((void**)&wif,  g_wif);
    cudaGetSymbolAddress((void**)&bif,  g_bif);

    const int SMEM_SZ = 2 * 32768 + 1024;
    cudaFuncSetAttribute(mma_gemm_kernel<false>,
                         cudaFuncAttributeMaxDynamicSharedMemorySize, SMEM_SZ);
    cudaFuncSetAttribute(mma_gemm_kernel<true>,
                         cudaFuncAttributeMaxDynamicSharedMemorySize, SMEM_SZ);

    // 1. LN + split
    ln_split_kernel<<<MROWS, 256>>>(x, gamma, beta);
    // 2. weight prep
    combine_if_kernel<<<(2 * HH * DD + 255) / 256, 256>>>(iw, ib, fw, fb);
    split_kernel<<<(DD * 256 + 255) / 256, 256>>>(qw, qw2, DD);
    split_kernel<<<(DD * 256 + 255) / 256, 256>>>(kw, kw2, DD);
    split_kernel<<<(DD * 256 + 255) / 256, 256>>>(vw, vw2, DD);
    split_kernel<<<(DD * 256 + 255) / 256, 256>>>(ow, ow2, DD);
    split_kernel<<<(2 * HH * 256 + 255) / 256, 256>>>(wif, wif2, 2 * HH);

    // 3. projections on tcgen05
    dim3 gridBig(DD / 128, MROWS / 128);   // (8, 256)
    dim3 gridIF(1, MROWS / 128);           // (1, 256)
    mma_gemm_kernel<false><<<gridBig, 256, SMEM_SZ>>>(a2, qw2, qb, nullptr, qp, DD, 1.0f);
    mma_gemm_kernel<false><<<gridBig, 256, SMEM_SZ>>>(a2, kw2, kb, nullptr, kp, DD, 0.25f);
    mma_gemm_kernel<false><<<gridBig, 256, SMEM_SZ>>>(a2, vw2, vb, nullptr, vp, DD, 1.0f);
    mma_gemm_kernel<false><<<gridIF, 256, SMEM_SZ>>>(a2, wif2, bif, nullptr, ifp, 2 * HH, 1.0f);

    // 4. sequential scan (writes split h directly)
    scan_kernel<<<256, 32>>>();

    // 5. output projection + residual
    mma_gemm_kernel<true><<<gridBig, 256, SMEM_SZ>>>(h2, ow2, ob, x, out, DD, 1.0f);
}

// round 5
// speedup vs baseline: 4.1878x; 2.0115x over previous
#include <cuda_runtime.h>
#include <cuda_bf16.h>
#include <cstdint>
#include <math.h>

#define BB 8
#define LL 4096
#define DD 1024
#define HH 64
#define HDIM 16
#define MROWS (BB*LL)        // 32768
#define KSPLIT 3072          // [hi | hi | lo] * 1024
#define KBYTES (KSPLIT*2)    // 6144 bytes per row
#define NCHUNKS (KSPLIT/64)  // 48 k-chunks in GEMM

#define CHUNK 64
#define NCH (LL/CHUNK)       // 64 time-chunks
#define NCHAINS (BB*HH)      // 512
#define NSUM (NCH*NCHAINS)   // 32768

#if defined(__CUDA_ARCH__) && (__CUDA_ARCH__ == 1030) && defined(__CUDA_ARCH_FEAT_SM103_ALL)
#define HAS_TCGEN05 1
#else
#define HAS_TCGEN05 0
#endif

// ---------------- device scratch ------------------------------------------
__device__ __nv_bfloat16 g_a2[(size_t)MROWS * KSPLIT];   // split xn
__device__ __nv_bfloat16 g_h2[(size_t)MROWS * KSPLIT];   // split hs
__device__ float g_q [(size_t)MROWS * DD];
__device__ float g_k [(size_t)MROWS * DD];
__device__ float g_v [(size_t)MROWS * DD];
__device__ float g_if[(size_t)MROWS * 2 * HH];
__device__ __nv_bfloat16 g_qw2[(size_t)DD * KSPLIT];
__device__ __nv_bfloat16 g_kw2[(size_t)DD * KSPLIT];
__device__ __nv_bfloat16 g_vw2[(size_t)DD * KSPLIT];
__device__ __nv_bfloat16 g_ow2[(size_t)DD * KSPLIT];
__device__ __nv_bfloat16 g_wif2[(size_t)(2*HH) * KSPLIT];
__device__ float g_wif[2 * HH * DD];
__device__ float g_bif[2 * HH];
// chunked-scan summaries / entering states
__device__ float g_Cloc[(size_t)NSUM * 256];
__device__ float g_nloc[(size_t)NSUM * 16];
__device__ float g_mloc[NSUM];
__device__ float g_Floc[NSUM];
__device__ float g_Cin [(size_t)NSUM * 256];
__device__ float g_nin [(size_t)NSUM * 16];
__device__ float g_min [NSUM];

// ---------------- PTX helpers (sm_103a only) -------------------------------
__device__ __forceinline__ uint32_t smem_u32(const void* p) {
    uint32_t a;
    asm("{ .reg .u64 t; cvta.to.shared.u64 t, %1; cvt.u32.u64 %0, t; }"
        : "=r"(a) : "l"(p));
    return a;
}

#if HAS_TCGEN05
__device__ __forceinline__ uint32_t elect_one_pred() {
    uint32_t pred;
    asm volatile("{\n\t.reg .pred p;\n\telect.sync _|p, 0xFFFFFFFF;\n\t"
                 "selp.b32 %0, 1, 0, p;\n\t}" : "=r"(pred));
    return pred;
}
#define TCGEN05_ALLOC(saddr, n) \
    asm volatile("tcgen05.alloc.cta_group::1.sync.aligned.shared::cta.b32 [%0], %1;" \
                 :: "r"((uint32_t)(saddr)), "r"((uint32_t)(n)) : "memory")
#define TCGEN05_DEALLOC(taddr, n) \
    asm volatile("tcgen05.dealloc.cta_group::1.sync.aligned.b32 %0, %1;" \
                 :: "r"(taddr), "r"((uint32_t)(n)))
#define TCGEN05_RELINQ() \
    asm volatile("tcgen05.relinquish_alloc_permit.cta_group::1.sync.aligned;")
#define TCGEN05_COMMIT(mbar) \
    asm volatile("tcgen05.commit.cta_group::1.mbarrier::arrive::one.shared::cluster.b64 [%0];" \
                 :: "r"((uint32_t)(mbar)) : "memory")
#define TCGEN05_FENCE_AFTER() \
    asm volatile("tcgen05.fence::after_thread_sync;" ::: "memory")
#define TCGEN05_FENCE_BEFORE() \
    asm volatile("tcgen05.fence::before_thread_sync;" ::: "memory")
#define TCGEN05_WAIT_LD() \
    asm volatile("tcgen05.wait::ld.sync.aligned;" ::: "memory")
#define FENCE_PROXY_ASYNC() \
    asm volatile("fence.proxy.async.shared::cta;" ::: "memory")
#define MBARRIER_INIT(mbar, cnt) \
    asm volatile("mbarrier.init.shared.b64 [%0], %1;" \
                 :: "r"((uint32_t)(mbar)), "r"((uint32_t)(cnt)) : "memory")
__device__ __forceinline__ void mbar_inval(uint32_t a) {
    asm volatile("mbarrier.inval.shared.b64 [%0];" :: "r"(a) : "memory");
}
#define MBARRIER_WAIT_PARITY(mbar, par) do { \
    uint32_t _m = (uint32_t)(mbar); uint32_t _p = (uint32_t)(par); uint32_t _d; \
    asm volatile("{\n\t.reg .pred p;\n\t" \
        "mbarrier.try_wait.parity.acquire.cta.shared::cta.b64 p, [%1], %2;\n\t" \
        "selp.b32 %0, 1, 0, p;\n\t}" : "=r"(_d) : "r"(_m), "r"(_p) : "memory"); \
    if (!_d) { \
        asm volatile("{\n\t.reg .pred P1;\n\t" \
            "WL_%=:\n\t" \
            "mbarrier.try_wait.parity.acquire.cta.shared::cta.b64 P1, [%0], %1, 0x989680;\n\t" \
            "@P1 bra.uni WD_%=;\n\tbra.uni WL_%=;\n\tWD_%=:\n\t}" \
            :: "r"(_m), "r"(_p) : "memory"); \
    } \
} while (0)
#define TCGEN05_MMA_F16_SS(dtm, adesc, bdesc, idesc, en) do { \
    uint32_t _e = (en) ? 1u : 0u; \
    asm volatile("{\n\t.reg .pred p;\n\tsetp.ne.u32 p, %5, 0;\n\t" \
        "tcgen05.mma.cta_group::1.kind::f16 [%0], %1, %2, %3, {%4, %4, %4, %4}, p;\n\t}" \
        :: "r"(dtm), "l"(adesc), "l"(bdesc), "r"(idesc), "r"(0u), "r"(_e) : "memory"); \
} while (0)
#define TCGEN05_LD_X32(r, taddr) \
    asm volatile("tcgen05.ld.sync.aligned.32x32b.x32.b32 " \
        "{%0, %1, %2, %3, %4, %5, %6, %7, %8, %9, %10, %11, %12, %13, %14, %15, " \
        "%16, %17, %18, %19, %20, %21, %22, %23, %24, %25, %26, %27, %28, %29, %30, %31}, [%32];" \
        : "=r"((r)[0]),  "=r"((r)[1]),  "=r"((r)[2]),  "=r"((r)[3]), \
          "=r"((r)[4]),  "=r"((r)[5]),  "=r"((r)[6]),  "=r"((r)[7]), \
          "=r"((r)[8]),  "=r"((r)[9]),  "=r"((r)[10]), "=r"((r)[11]), \
          "=r"((r)[12]), "=r"((r)[13]), "=r"((r)[14]), "=r"((r)[15]), \
          "=r"((r)[16]), "=r"((r)[17]), "=r"((r)[18]), "=r"((r)[19]), \
          "=r"((r)[20]), "=r"((r)[21]), "=r"((r)[22]), "=r"((r)[23]), \
          "=r"((r)[24]), "=r"((r)[25]), "=r"((r)[26]), "=r"((r)[27]), \
          "=r"((r)[28]), "=r"((r)[29]), "=r"((r)[30]), "=r"((r)[31]) \
        : "r"(taddr))

static constexpr uint64_t SMEM_DESC_BASE_SW128 =
    (uint64_t(2)  << 61) | (uint64_t(1) << 46) | (uint64_t(64) << 32) | (uint64_t(1) << 16);
#define MAKE_SMEM_DESC(a) (SMEM_DESC_BASE_SW128 | ((uint64_t)((a) >> 4) & 0x3FFF))

static constexpr uint32_t MMA_IDESC =
    (1u << 4) | (1u << 7) | (1u << 10) | ((128u / 8) << 17) | ((128u / 16) << 24);
#endif  // HAS_TCGEN05

#define SWZ128(off) ((off) ^ (((off) >> 3) & 0x70))

// ---------------- bf16 split helper ----------------------------------------
__device__ __forceinline__ void split2(float v, __nv_bfloat16& hi, __nv_bfloat16& lo) {
    hi = __float2bfloat16(v);
    lo = __float2bfloat16(v - __bfloat162float(hi));
}

// ---------------- LayerNorm fused with bf16 split output --------------------
__global__ void ln_split_kernel(const float* __restrict__ x,
                                const float* __restrict__ gamma,
                                const float* __restrict__ beta) {
    __shared__ float s_sum[8], s_sq[8];
    const int row = blockIdx.x;
    const float4* xr = reinterpret_cast<const float4*>(x) + (size_t)row * (DD / 4);
    float4 v = xr[threadIdx.x];
    float s = v.x + v.y + v.z + v.w;
    float q = v.x * v.x + v.y * v.y + v.z * v.z + v.w * v.w;
    #pragma unroll
    for (int o = 16; o; o >>= 1) {
        s += __shfl_xor_sync(0xffffffffu, s, o);
        q += __shfl_xor_sync(0xffffffffu, q, o);
    }
    const int warp = threadIdx.x >> 5, lane = threadIdx.x & 31;
    if (lane == 0) { s_sum[warp] = s; s_sq[warp] = q; }
    __syncthreads();
    if (warp == 0) {
        s = (lane < 8) ? s_sum[lane] : 0.f;
        q = (lane < 8) ? s_sq[lane] : 0.f;
        #pragma unroll
        for (int o = 4; o; o >>= 1) {
            s += __shfl_xor_sync(0xffffffffu, s, o);
            q += __shfl_xor_sync(0xffffffffu, q, o);
        }
        if (lane == 0) { s_sum[0] = s; s_sq[0] = q; }
    }
    __syncthreads();
    const float mean = s_sum[0] * (1.f / DD);
    const float var  = s_sq[0] * (1.f / DD) - mean * mean;
    const float rstd = rsqrtf(var + 1e-5f);
    const float4 gg = reinterpret_cast<const float4*>(gamma)[threadIdx.x];
    const float4 bb = reinterpret_cast<const float4*>(beta)[threadIdx.x];
    float o0 = (v.x - mean) * rstd * gg.x + bb.x;
    float o1 = (v.y - mean) * rstd * gg.y + bb.y;
    float o2 = (v.z - mean) * rstd * gg.z + bb.z;
    float o3 = (v.w - mean) * rstd * gg.w + bb.w;
    __nv_bfloat16 h0, h1, h2, h3, l0, l1, l2, l3;
    split2(o0, h0, l0); split2(o1, h1, l1); split2(o2, h2, l2); split2(o3, h3, l3);
    __nv_bfloat16* dst = g_a2 + (size_t)row * KSPLIT + threadIdx.x * 4;
    __nv_bfloat162* d0 = reinterpret_cast<__nv_bfloat162*>(dst);
    __nv_bfloat162* d1 = reinterpret_cast<__nv_bfloat162*>(dst + 1024);
    __nv_bfloat162* d2 = reinterpret_cast<__nv_bfloat162*>(dst + 2048);
    __nv_bfloat162 hA(h0, h1), hB(h2, h3), lA(l0, l1), lB(l2, l3);
    d0[0] = hA; d0[1] = hB;
    d1[0] = hA; d1[1] = hB;
    d2[0] = lA; d2[1] = lB;
}

// ---------------- generic fp32 -> split-bf16 [rows,3072] (B-side) -----------
__global__ void split_kernel(const float* __restrict__ src, __nv_bfloat16* __restrict__ dst,
                             int rows) {
    int i = blockIdx.x * blockDim.x + threadIdx.x;
    if (i >= rows * 256) return;
    int row = i >> 8;
    int g = i & 255;
    float4 v = reinterpret_cast<const float4*>(src + (size_t)row * DD)[g];
    __nv_bfloat16 h0, h1, h2, h3, l0, l1, l2, l3;
    split2(v.x, h0, l0); split2(v.y, h1, l1); split2(v.z, h2, l2); split2(v.w, h3, l3);
    __nv_bfloat16* d = dst + (size_t)row * KSPLIT + g * 4;
    __nv_bfloat162 hA(h0, h1), hB(h2, h3), lA(l0, l1), lB(l2, l3);
    reinterpret_cast<__nv_bfloat162*>(d)[0] = hA;
    reinterpret_cast<__nv_bfloat162*>(d)[1] = hB;
    reinterpret_cast<__nv_bfloat162*>(d + 1024)[0] = lA;   // B-side order: [hi | lo | hi]
    reinterpret_cast<__nv_bfloat162*>(d + 1024)[1] = lB;
    reinterpret_cast<__nv_bfloat162*>(d + 2048)[0] = hA;
    reinterpret_cast<__nv_bfloat162*>(d + 2048)[1] = hB;
}

// ---------------- pack i/f weights -----------------------------------------
__global__ void combine_if_kernel(const float* __restrict__ iw,
                                  const float* __restrict__ ib,
                                  const float* __restrict__ fw,
                                  const float* __restrict__ fb) {
    int idx = blockIdx.x * blockDim.x + threadIdx.x;
    if (idx < 2 * HH * DD) {
        int nrow = idx / DD;
        g_wif[idx] = (nrow < HH) ? iw[idx] : fw[idx - HH * DD];
    }
    if (idx < 2 * HH) g_bif[idx] = (idx < HH) ? ib[idx] : fb[idx - HH];
}

// ---------------- tcgen05 GEMM (unchanged from round 4) ---------------------
template <bool RESID>
__global__ void __launch_bounds__(256, 2) mma_gemm_kernel(
    const __nv_bfloat16* __restrict__ A2,
    const __nv_bfloat16* __restrict__ B2,
    const float* __restrict__ bias,
    const float* __restrict__ resid,
    float* __restrict__ out,
    int N, float scale)
{
#if HAS_TCGEN05
    extern __shared__ char smem_raw[];
    char* smem = (char*)(((uintptr_t)smem_raw + 1023) & ~(uintptr_t)1023);
    __shared__ __align__(16) uint64_t s_mbar[2];
    __shared__ uint32_t s_tmem;

    const int tid = threadIdx.x;
    const int wid = tid >> 5;
    const int bm = blockIdx.y * 128;
    const int bn = blockIdx.x * 128;
    const uint32_t smem_base = smem_u32(smem);

    if (wid == 0) {
        TCGEN05_ALLOC(smem_u32(&s_tmem), 128);
        TCGEN05_RELINQ();
    }
    if (tid == 0) {
        MBARRIER_INIT(smem_u32(&s_mbar[0]), 1);
        MBARRIER_INIT(smem_u32(&s_mbar[1]), 1);
    }
    __syncthreads();
    const uint32_t tmem_d = s_tmem;
    const uint32_t mbar0 = smem_u32(&s_mbar[0]);
    const uint32_t mbar1 = smem_u32(&s_mbar[1]);

    const char* Abase = (const char*)(A2 + (size_t)bm * KSPLIT);
    const char* Bbase = (const char*)(B2 + (size_t)bn * KSPLIT);

    auto load_chunk = [&](int kc, int s) {
        const char* ag = Abase + (size_t)kc * 128;
        const char* bg = Bbase + (size_t)kc * 128;
        char* sa = smem + s * 32768;
        char* sb = sa + 16384;
        #pragma unroll
        for (int i = 0; i < 4; ++i) {
            int cidx = tid + i * 256;
            int row = cidx >> 3;
            int c16 = cidx & 7;
            uint4 va = *(const uint4*)(ag + (size_t)row * KBYTES + c16 * 16);
            uint4 vb = *(const uint4*)(bg + (size_t)row * KBYTES + c16 * 16);
            uint32_t off = row * 128 + c16 * 16;
            uint32_t sw = SWZ128(off);
            *(uint4*)(sa + sw) = va;
            *(uint4*)(sb + sw) = vb;
        }
    };

    load_chunk(0, 0);
    __syncthreads();

    int phase0 = 0, phase1 = 0;
    for (int kc = 0; kc < NCHUNKS; ++kc) {
        const int s = kc & 1;
        if (wid == 0) {
            FENCE_PROXY_ASYNC();
            if (elect_one_pred()) {
                uint64_t ad = MAKE_SMEM_DESC(smem_base + s * 32768);
                uint64_t bd = MAKE_SMEM_DESC(smem_base + s * 32768 + 16384);
                #pragma unroll
                for (int j = 0; j < 4; ++j)
                    TCGEN05_MMA_F16_SS(tmem_d, ad + j * 2, bd + j * 2, MMA_IDESC,
                                       (kc > 0) || (j > 0));
                TCGEN05_COMMIT(s == 0 ? mbar0 : mbar1);
            }
        }
        if (kc + 1 < NCHUNKS) {
            const int s2 = (kc + 1) & 1;
            if (kc >= 1) {
                if (s2 == 0) { MBARRIER_WAIT_PARITY(mbar0, phase0); phase0 ^= 1; }
                else         { MBARRIER_WAIT_PARITY(mbar1, phase1); phase1 ^= 1; }
            }
            load_chunk(kc + 1, s2);
        }
        __syncthreads();
    }
    MBARRIER_WAIT_PARITY(mbar1, phase1);
    TCGEN05_FENCE_AFTER();

    const int colbase = (wid >> 2) * 64;
    const int row = bm + (wid & 3) * 32 + (tid & 31);
    #pragma unroll
    for (int cb = 0; cb < 64; cb += 32) {
        uint32_t dr[32];
        TCGEN05_LD_X32(dr, tmem_d + colbase + cb);
        TCGEN05_WAIT_LD();
        TCGEN05_FENCE_BEFORE();
        #pragma unroll
        for (int c = 0; c < 32; c += 4) {
            const int col = bn + colbase + cb + c;
            float4 bs = *(const float4*)(bias + col);
            float4 o;
            o.x = scale * (__uint_as_float(dr[c + 0]) + bs.x);
            o.y = scale * (__uint_as_float(dr[c + 1]) + bs.y);
            o.z = scale * (__uint_as_float(dr[c + 2]) + bs.z);
            o.w = scale * (__uint_as_float(dr[c + 3]) + bs.w);
            if (RESID) {
                float4 r = *(const float4*)(resid + (size_t)row * N + col);
                o.x += r.x; o.y += r.y; o.z += r.z; o.w += r.w;
            }
            *(float4*)(out + (size_t)row * N + col) = o;
        }
    }
    __syncthreads();
    if (tid == 0) { mbar_inval(mbar0); mbar_inval(mbar1); }
    __syncthreads();
    if (wid == 0) TCGEN05_DEALLOC(tmem_d, 128);
#else
    // Fallback for the compute_103 PTX pass (never run on sm_103a HW).
    const int tid = threadIdx.x;
    const int bm = blockIdx.y * 128;
    const int bn = blockIdx.x * 128;
    const int r0 = (tid >> 4) * 8;
    const int c0 = (tid & 15) * 8;
    for (int i = 0; i < 8; ++i) {
        const int row = bm + r0 + i;
        const __nv_bfloat16* ar = A2 + (size_t)row * KSPLIT;
        for (int j = 0; j < 8; ++j) {
            const int col = bn + c0 + j;
            const __nv_bfloat16* br = B2 + (size_t)col * KSPLIT;
            float acc = 0.f;
            for (int k = 0; k < KSPLIT; ++k)
                acc += __bfloat162float(ar[k]) * __bfloat162float(br[k]);
            float o = scale * (acc + bias[col]);
            if (RESID) o += resid[(size_t)row * N + col];
            out[(size_t)row * N + col] = o;
        }
    }
#endif
}

// ---------------- chunked scan, phase 1: per-chunk local scan ---------------
// 16 lanes per (chain, chunk); lane e holds C[:, e]. Init (0, 0, -inf).
__global__ void __launch_bounds__(256) scan_phase1_kernel() {
    const int tid = threadIdx.x;
    const int gid = blockIdx.x * 16 + (tid >> 4);   // 0..NSUM-1
    const int e = tid & 15;
    const int j = gid >> 9;          // chunk
    const int c = gid & 511;         // chain
    const int b = c >> 6, h = c & 63;
    const int t0 = j * CHUNK;

    size_t off = ((size_t)b * LL + t0) * DD + h * HDIM + e;
    size_t offIF = ((size_t)b * LL + t0) * (2 * HH);

    float C[16];
    #pragma unroll
    for (int d = 0; d < 16; ++d) C[d] = 0.f;
    float n = 0.f, m = -1e30f, F = 0.f;

    for (int t = 0; t < CHUNK; ++t) {
        const float ke = g_k[off], ve = g_v[off];
        const float it = g_if[offIF + h];
        const float ft = g_if[offIF + HH + h];
        const float m_new = fmaxf(ft + m, it);
        const float fd = __expf(ft + m - m_new);
        const float id = __expf(it - m_new);
        m = m_new; F += ft;
        const float kid = id * ke;
        n = fd * n + kid;
        #pragma unroll
        for (int d = 0; d < 16; ++d) {
            const float vd = __shfl_sync(0xffffffffu, ve, d, 16);
            C[d] = fd * C[d] + vd * kid;
        }
        off += DD; offIF += 2 * HH;
    }
    float* cs = g_Cloc + (size_t)gid * 256;
    #pragma unroll
    for (int d = 0; d < 16; ++d) cs[d * 16 + e] = C[d];
    g_nloc[(size_t)gid * 16 + e] = n;
    if (e == 0) { g_mloc[gid] = m; g_Floc[gid] = F; }
}

// ---------------- phase 2: serial combine across chunks (per chain) ---------
__global__ void __launch_bounds__(256) scan_phase2_kernel() {
    const int tid = threadIdx.x;
    const int c = blockIdx.x * 16 + (tid >> 4);     // chain 0..511
    const int e = tid & 15;

    float C[16];
    #pragma unroll
    for (int d = 0; d < 16; ++d) C[d] = 0.f;
    float n = 0.f, m = 0.f;                          // reference init: zeros

    for (int j = 0; j < NCH; ++j) {
        const int sid = j * NCHAINS + c;
        // store entering state for chunk j
        float* ci = g_Cin + (size_t)sid * 256;
        #pragma unroll
        for (int d = 0; d < 16; ++d) ci[d * 16 + e] = C[d];
        g_nin[(size_t)sid * 16 + e] = n;
        if (e == 0) g_min[sid] = m;
        // combine with chunk-local summary
        const float ml = g_mloc[sid];
        const float F  = g_Floc[sid];
        const float mo = fmaxf(m + F, ml);
        const float a  = __expf(m + F - mo);   // exponent <= 0
        const float bb = __expf(ml - mo);      // exponent <= 0
        const float* cl = g_Cloc + (size_t)sid * 256;
        #pragma unroll
        for (int d = 0; d < 16; ++d) C[d] = a * C[d] + bb * cl[d * 16 + e];
        n = a * n + bb * g_nloc[(size_t)sid * 16 + e];
        m = mo;
    }
}

// ---------------- phase 3: replay chunk from entering state, emit h ---------
__global__ void __launch_bounds__(256) scan_phase3_kernel() {
    const int tid = threadIdx.x;
    const int gid = blockIdx.x * 16 + (tid >> 4);
    const int e = tid & 15;
    const int j = gid >> 9;
    const int c = gid & 511;
    const int b = c >> 6, h = c & 63;
    const int t0 = j * CHUNK;

    size_t off = ((size_t)b * LL + t0) * DD + h * HDIM + e;
    size_t offIF = ((size_t)b * LL + t0) * (2 * HH);
    size_t h2off = ((size_t)b * LL + t0) * KSPLIT + h * HDIM + e;

    const float* ci = g_Cin + (size_t)gid * 256;
    float C[16];
    #pragma unroll
    for (int d = 0; d < 16; ++d) C[d] = ci[d * 16 + e];
    float n = g_nin[(size_t)gid * 16 + e];
    float m = g_min[gid];

    for (int t = 0; t < CHUNK; ++t) {
        const float qe = g_q[off], ke = g_k[off], ve = g_v[off];
        const float it = g_if[offIF + h];
        const float ft = g_if[offIF + HH + h];
        const float m_new = fmaxf(ft + m, it);
        const float fd = __expf(ft + m - m_new);
        const float id = __expf(it - m_new);
        m = m_new;
        const float kid = id * ke;
        n = fd * n + kid;

        float cq = 0.f;
        #pragma unroll
        for (int d = 0; d < 16; ++d) {
            const float vd = __shfl_sync(0xffffffffu, ve, d, 16);
            const float qd = __shfl_sync(0xffffffffu, qe, d, 16);
            C[d] = fd * C[d] + vd * kid;
            cq = fmaf(C[d], qd, cq);
        }

        float nq = n * qe;
        #pragma unroll
        for (int o = 8; o; o >>= 1) nq += __shfl_xor_sync(0xffffffffu, nq, o, 16);
        const float denom = fmaxf(fabsf(nq), 1.0f);

        const float hval = cq / denom;
        __nv_bfloat16 hh, hl;
        split2(hval, hh, hl);
        g_h2[h2off] = hh;
        g_h2[h2off + 1024] = hh;
        g_h2[h2off + 2048] = hl;

        off += DD; offIF += 2 * HH; h2off += KSPLIT;
    }
}

// ---------------- launch ----------------------------------------------------
extern "C" void kernel_launch(void* const* d_in, const int* in_sizes, int n_in,
                              void* d_out, int out_size) {
    (void)in_sizes; (void)n_in; (void)out_size;
    const float* x     = (const float*)d_in[0];
    const float* gamma = (const float*)d_in[1];
    const float* beta  = (const float*)d_in[2];
    const float* qw    = (const float*)d_in[3];
    const float* qb    = (const float*)d_in[4];
    const float* kw    = (const float*)d_in[5];
    const float* kb    = (const float*)d_in[6];
    const float* vw    = (const float*)d_in[7];
    const float* vb    = (const float*)d_in[8];
    const float* ow    = (const float*)d_in[9];
    const float* ob    = (const float*)d_in[10];
    const float* iw    = (const float*)d_in[11];
    const float* ib    = (const float*)d_in[12];
    const float* fw    = (const float*)d_in[13];
    const float* fb    = (const float*)d_in[14];
    float* out = (float*)d_out;

    __nv_bfloat16 *a2, *h2, *qw2, *kw2, *vw2, *ow2, *wif2;
    float *qp, *kp, *vp, *ifp, *wif, *bif;
    cudaGetSymbolAddress((void**)&a2,   g_a2);
    cudaGetSymbolAddress((void**)&h2,   g_h2);
    cudaGetSymbolAddress((void**)&qw2,  g_qw2);
    cudaGetSymbolAddress((void**)&kw2,  g_kw2);
    cudaGetSymbolAddress((void**)&vw2,  g_vw2);
    cudaGetSymbolAddress((void**)&ow2,  g_ow2);
    cudaGetSymbolAddress((void**)&wif2, g_wif2);
    cudaGetSymbolAddress((void**)&qp,   g_q);
    cudaGetSymbolAddress((void**)&kp,   g_k);
    cudaGetSymbolAddress((void**)&vp,   g_v);
    cudaGetSymbolAddress((void**)&ifp,  g_if);
    cudaGetSymbolAddress((void**)&wif,  g_wif);
    cudaGetSymbolAddress((void**)&bif,  g_bif);

    const int SMEM_SZ = 2 * 32768 + 1024;
    cudaFuncSetAttribute(mma_gemm_kernel<false>,
                         cudaFuncAttributeMaxDynamicSharedMemorySize, SMEM_SZ);
    cudaFuncSetAttribute(mma_gemm_kernel<true>,
                         cudaFuncAttributeMaxDynamicSharedMemorySize, SMEM_SZ);

    // 1. LN + split
    ln_split_kernel<<<MROWS, 256>>>(x, gamma, beta);
    // 2. weight prep
    combine_if_kernel<<<(2 * HH * DD + 255) / 256, 256>>>(iw, ib, fw, fb);
    split_kernel<<<(DD * 256 + 255) / 256, 256>>>(qw, qw2, DD);
    split_kernel<<<(DD * 256 + 255) / 256, 256>>>(kw, kw2, DD);
    split_kernel<<<(DD * 256 + 255) / 256, 256>>>(vw, vw2, DD);
    split_kernel<<<(DD * 256 + 255) / 256, 256>>>(ow, ow2, DD);
    split_kernel<<<(2 * HH * 256 + 255) / 256, 256>>>(wif, wif2, 2 * HH);

    // 3. projections on tcgen05
    dim3 gridBig(DD / 128, MROWS / 128);   // (8, 256)
    dim3 gridIF(1, MROWS / 128);           // (1, 256)
    mma_gemm_kernel<false><<<gridBig, 256, SMEM_SZ>>>(a2, qw2, qb, nullptr, qp, DD, 1.0f);
    mma_gemm_kernel<false><<<gridBig, 256, SMEM_SZ>>>(a2, kw2, kb, nullptr, kp, DD, 0.25f);
    mma_gemm_kernel<false><<<gridBig, 256, SMEM_SZ>>>(a2, vw2, vb, nullptr, vp, DD, 1.0f);
    mma_gemm_kernel<false><<<gridIF, 256, SMEM_SZ>>>(a2, wif2, bif, nullptr, ifp, 2 * HH, 1.0f);

    // 4. chunked parallel scan
    scan_phase1_kernel<<<NSUM / 16, 256>>>();
    scan_phase2_kernel<<<NCHAINS / 16, 256>>>();
    scan_phase3_kernel<<<NSUM / 16, 256>>>();

    // 5. output projection + residual
    mma_gemm_kernel<true><<<gridBig, 256, SMEM_SZ>>>(h2, ow2, ob, x, out, DD, 1.0f);
}

// round 7
// speedup vs baseline: 5.2963x; 1.2647x over previous
#include <cuda_runtime.h>
#include <cuda_bf16.h>
#include <cstdint>
#include <math.h>

#define BB 8
#define LL 4096
#define DD 1024
#define HH 64
#define HDIM 16
#define MROWS (BB*LL)        // 32768
#define KSP2 2048            // [hi | lo] * 1024
#define ROWB 4096            // bytes per [hi|lo] row
#define NSTEP 16             // 1024/64 k-steps in GEMM

#define CHUNK 64
#define NCH (LL/CHUNK)       // 64 time-chunks
#define NCHAINS (BB*HH)      // 512
#define NSUM (NCH*NCHAINS)   // 32768

#define STAGE 98304          // 96KB: Ah,Al,B0h,B0l,B1h,B1l (16KB each)
#define SMEM_SZ (2*STAGE + 1024)

#if defined(__CUDA_ARCH__) && (__CUDA_ARCH__ == 1030) && defined(__CUDA_ARCH_FEAT_SM103_ALL)
#define HAS_TCGEN05 1
#else
#define HAS_TCGEN05 0
#endif

// ---------------- device scratch ------------------------------------------
__device__ __nv_bfloat16 g_a2[(size_t)MROWS * KSP2];   // split xn [hi|lo]
__device__ __nv_bfloat16 g_h2[(size_t)MROWS * KSP2];   // split hs [hi|lo]
__device__ float g_q [(size_t)MROWS * DD];
__device__ float g_k [(size_t)MROWS * DD];
__device__ float g_v [(size_t)MROWS * DD];
__device__ float g_if[(size_t)MROWS * 2 * HH];
__device__ __nv_bfloat16 g_qw2[(size_t)DD * KSP2];
__device__ __nv_bfloat16 g_kw2[(size_t)DD * KSP2];
__device__ __nv_bfloat16 g_vw2[(size_t)DD * KSP2];
__device__ __nv_bfloat16 g_ow2[(size_t)DD * KSP2];
__device__ __nv_bfloat16 g_wif2[(size_t)(2*HH) * KSP2];
__device__ float g_wif[2 * HH * DD];
__device__ float g_bif[2 * HH];
// chunked-scan summaries / entering states
__device__ float g_Cloc[(size_t)NSUM * 256];
__device__ float g_nloc[(size_t)NSUM * 16];
__device__ float g_mloc[NSUM];
__device__ float g_Floc[NSUM];
__device__ float g_Cin [(size_t)NSUM * 256];
__device__ float g_nin [(size_t)NSUM * 16];
__device__ float g_min [NSUM];

// ---------------- PTX helpers (sm_103a only) -------------------------------
__device__ __forceinline__ uint32_t smem_u32(const void* p) {
    uint32_t a;
    asm("{ .reg .u64 t; cvta.to.shared.u64 t, %1; cvt.u32.u64 %0, t; }"
        : "=r"(a) : "l"(p));
    return a;
}

#if HAS_TCGEN05
__device__ __forceinline__ uint32_t elect_one_pred() {
    uint32_t pred;
    asm volatile("{\n\t.reg .pred p;\n\telect.sync _|p, 0xFFFFFFFF;\n\t"
                 "selp.b32 %0, 1, 0, p;\n\t}" : "=r"(pred));
    return pred;
}
#define TCGEN05_ALLOC(saddr, n) \
    asm volatile("tcgen05.alloc.cta_group::1.sync.aligned.shared::cta.b32 [%0], %1;" \
                 :: "r"((uint32_t)(saddr)), "r"((uint32_t)(n)) : "memory")
#define TCGEN05_DEALLOC(taddr, n) \
    asm volatile("tcgen05.dealloc.cta_group::1.sync.aligned.b32 %0, %1;" \
                 :: "r"(taddr), "r"((uint32_t)(n)))
#define TCGEN05_RELINQ() \
    asm volatile("tcgen05.relinquish_alloc_permit.cta_group::1.sync.aligned;")
#define TCGEN05_COMMIT(mbar) \
    asm volatile("tcgen05.commit.cta_group::1.mbarrier::arrive::one.shared::cluster.b64 [%0];" \
                 :: "r"((uint32_t)(mbar)) : "memory")
#define TCGEN05_FENCE_AFTER() \
    asm volatile("tcgen05.fence::after_thread_sync;" ::: "memory")
#define TCGEN05_FENCE_BEFORE() \
    asm volatile("tcgen05.fence::before_thread_sync;" ::: "memory")
#define TCGEN05_WAIT_LD() \
    asm volatile("tcgen05.wait::ld.sync.aligned;" ::: "memory")
#define FENCE_PROXY_ASYNC() \
    asm volatile("fence.proxy.async.shared::cta;" ::: "memory")
#define MBARRIER_INIT(mbar, cnt) \
    asm volatile("mbarrier.init.shared.b64 [%0], %1;" \
                 :: "r"((uint32_t)(mbar)), "r"((uint32_t)(cnt)) : "memory")
__device__ __forceinline__ void mbar_inval(uint32_t a) {
    asm volatile("mbarrier.inval.shared.b64 [%0];" :: "r"(a) : "memory");
}
#define MBARRIER_WAIT_PARITY(mbar, par) do { \
    uint32_t _m = (uint32_t)(mbar); uint32_t _p = (uint32_t)(par); uint32_t _d; \
    asm volatile("{\n\t.reg .pred p;\n\t" \
        "mbarrier.try_wait.parity.acquire.cta.shared::cta.b64 p, [%1], %2;\n\t" \
        "selp.b32 %0, 1, 0, p;\n\t}" : "=r"(_d) : "r"(_m), "r"(_p) : "memory"); \
    if (!_d) { \
        asm volatile("{\n\t.reg .pred P1;\n\t" \
            "WL_%=:\n\t" \
            "mbarrier.try_wait.parity.acquire.cta.shared::cta.b64 P1, [%0], %1, 0x989680;\n\t" \
            "@P1 bra.uni WD_%=;\n\tbra.uni WL_%=;\n\tWD_%=:\n\t}" \
            :: "r"(_m), "r"(_p) : "memory"); \
    } \
} while (0)
#define TCGEN05_MMA_F16_SS(dtm, adesc, bdesc, idesc, en) do { \
    uint32_t _e = (en) ? 1u : 0u; \
    asm volatile("{\n\t.reg .pred p;\n\tsetp.ne.u32 p, %5, 0;\n\t" \
        "tcgen05.mma.cta_group::1.kind::f16 [%0], %1, %2, %3, {%4, %4, %4, %4}, p;\n\t}" \
        :: "r"(dtm), "l"(adesc), "l"(bdesc), "r"(idesc), "r"(0u), "r"(_e) : "memory"); \
} while (0)
#define TCGEN05_LD_X32(r, taddr) \
    asm volatile("tcgen05.ld.sync.aligned.32x32b.x32.b32 " \
        "{%0, %1, %2, %3, %4, %5, %6, %7, %8, %9, %10, %11, %12, %13, %14, %15, " \
        "%16, %17, %18, %19, %20, %21, %22, %23, %24, %25, %26, %27, %28, %29, %30, %31}, [%32];" \
        : "=r"((r)[0]),  "=r"((r)[1]),  "=r"((r)[2]),  "=r"((r)[3]), \
          "=r"((r)[4]),  "=r"((r)[5]),  "=r"((r)[6]),  "=r"((r)[7]), \
          "=r"((r)[8]),  "=r"((r)[9]),  "=r"((r)[10]), "=r"((r)[11]), \
          "=r"((r)[12]), "=r"((r)[13]), "=r"((r)[14]), "=r"((r)[15]), \
          "=r"((r)[16]), "=r"((r)[17]), "=r"((r)[18]), "=r"((r)[19]), \
          "=r"((r)[20]), "=r"((r)[21]), "=r"((r)[22]), "=r"((r)[23]), \
          "=r"((r)[24]), "=r"((r)[25]), "=r"((r)[26]), "=r"((r)[27]), \
          "=r"((r)[28]), "=r"((r)[29]), "=r"((r)[30]), "=r"((r)[31]) \
        : "r"(taddr))

static constexpr uint64_t SMEM_DESC_BASE_SW128 =
    (uint64_t(2)  << 61) | (uint64_t(1) << 46) | (uint64_t(64) << 32) | (uint64_t(1) << 16);
#define MAKE_SMEM_DESC(a) (SMEM_DESC_BASE_SW128 | ((uint64_t)((a) >> 4) & 0x3FFF))

// idesc: f32 accum, bf16 A/B, M=128, N=128
static constexpr uint32_t MMA_IDESC =
    (1u << 4) | (1u << 7) | (1u << 10) | ((128u / 8) << 17) | ((128u / 16) << 24);
#endif  // HAS_TCGEN05

#define SWZ128(off) ((off) ^ (((off) >> 3) & 0x70))

// ---------------- bf16 split helper ----------------------------------------
__device__ __forceinline__ void split2(float v, __nv_bfloat16& hi, __nv_bfloat16& lo) {
    hi = __float2bfloat16(v);
    lo = __float2bfloat16(v - __bfloat162float(hi));
}

// ---------------- LayerNorm fused with [hi|lo] bf16 output ------------------
__global__ void ln_split_kernel(const float* __restrict__ x,
                                const float* __restrict__ gamma,
                                const float* __restrict__ beta) {
    __shared__ float s_sum[8], s_sq[8];
    const int row = blockIdx.x;
    const float4* xr = reinterpret_cast<const float4*>(x) + (size_t)row * (DD / 4);
    float4 v = xr[threadIdx.x];
    float s = v.x + v.y + v.z + v.w;
    float q = v.x * v.x + v.y * v.y + v.z * v.z + v.w * v.w;
    #pragma unroll
    for (int o = 16; o; o >>= 1) {
        s += __shfl_xor_sync(0xffffffffu, s, o);
        q += __shfl_xor_sync(0xffffffffu, q, o);
    }
    const int warp = threadIdx.x >> 5, lane = threadIdx.x & 31;
    if (lane == 0) { s_sum[warp] = s; s_sq[warp] = q; }
    __syncthreads();
    if (warp == 0) {
        s = (lane < 8) ? s_sum[lane] : 0.f;
        q = (lane < 8) ? s_sq[lane] : 0.f;
        #pragma unroll
        for (int o = 4; o; o >>= 1) {
            s += __shfl_xor_sync(0xffffffffu, s, o);
            q += __shfl_xor_sync(0xffffffffu, q, o);
        }
        if (lane == 0) { s_sum[0] = s; s_sq[0] = q; }
    }
    __syncthreads();
    const float mean = s_sum[0] * (1.f / DD);
    const float var  = s_sq[0] * (1.f / DD) - mean * mean;
    const float rstd = rsqrtf(var + 1e-5f);
    const float4 gg = reinterpret_cast<const float4*>(gamma)[threadIdx.x];
    const float4 bb = reinterpret_cast<const float4*>(beta)[threadIdx.x];
    float o0 = (v.x - mean) * rstd * gg.x + bb.x;
    float o1 = (v.y - mean) * rstd * gg.y + bb.y;
    float o2 = (v.z - mean) * rstd * gg.z + bb.z;
    float o3 = (v.w - mean) * rstd * gg.w + bb.w;
    __nv_bfloat16 h0, h1, h2, h3, l0, l1, l2, l3;
    split2(o0, h0, l0); split2(o1, h1, l1); split2(o2, h2, l2); split2(o3, h3, l3);
    __nv_bfloat16* dst = g_a2 + (size_t)row * KSP2 + threadIdx.x * 4;
    __nv_bfloat162 hA(h0, h1), hB(h2, h3), lA(l0, l1), lB(l2, l3);
    reinterpret_cast<__nv_bfloat162*>(dst)[0] = hA;
    reinterpret_cast<__nv_bfloat162*>(dst)[1] = hB;
    reinterpret_cast<__nv_bfloat162*>(dst + 1024)[0] = lA;
    reinterpret_cast<__nv_bfloat162*>(dst + 1024)[1] = lB;
}

// ---------------- generic fp32 -> [hi|lo] bf16 [rows,2048] ------------------
__global__ void split_kernel(const float* __restrict__ src, __nv_bfloat16* __restrict__ dst,
                             int rows) {
    int i = blockIdx.x * blockDim.x + threadIdx.x;
    if (i >= rows * 256) return;
    int row = i >> 8;
    int g = i & 255;
    float4 v = reinterpret_cast<const float4*>(src + (size_t)row * DD)[g];
    __nv_bfloat16 h0, h1, h2, h3, l0, l1, l2, l3;
    split2(v.x, h0, l0); split2(v.y, h1, l1); split2(v.z, h2, l2); split2(v.w, h3, l3);
    __nv_bfloat16* d = dst + (size_t)row * KSP2 + g * 4;
    __nv_bfloat162 hA(h0, h1), hB(h2, h3), lA(l0, l1), lB(l2, l3);
    reinterpret_cast<__nv_bfloat162*>(d)[0] = hA;
    reinterpret_cast<__nv_bfloat162*>(d)[1] = hB;
    reinterpret_cast<__nv_bfloat162*>(d + 1024)[0] = lA;
    reinterpret_cast<__nv_bfloat162*>(d + 1024)[1] = lB;
}

// ---------------- pack i/f weights -----------------------------------------
__global__ void combine_if_kernel(const float* __restrict__ iw,
                                  const float* __restrict__ ib,
                                  const float* __restrict__ fw,
                                  const float* __restrict__ fb) {
    int idx = blockIdx.x * blockDim.x + threadIdx.x;
    if (idx < 2 * HH * DD) {
        int nrow = idx / DD;
        g_wif[idx] = (nrow < HH) ? iw[idx] : fw[idx - HH * DD];
    }
    if (idx < 2 * HH) g_bif[idx] = (idx < HH) ? ib[idx] : fb[idx - HH];
}

// ---------------- tcgen05 GEMM, [hi|lo] operands, 2 N-tiles per CTA ---------
// out[m,n] = scale*(Ah·Bh + Ah·Bl + Al·Bh + bias) (+resid)
// A2: [M, 2048] bf16 (hi|lo), B2: [N, 2048] bf16 (hi|lo)
template <bool RESID>
__global__ void __launch_bounds__(256, 1) mma_gemm_kernel(
    const __nv_bfloat16* __restrict__ A2,
    const __nv_bfloat16* __restrict__ B2,
    const float* __restrict__ bias,
    const float* __restrict__ resid,
    float* __restrict__ out,
    int N, float scale, int ntiles)
{
#if HAS_TCGEN05
    extern __shared__ char smem_raw[];
    char* smem = (char*)(((uintptr_t)smem_raw + 1023) & ~(uintptr_t)1023);
    __shared__ __align__(16) uint64_t s_mbar[2];
    __shared__ uint32_t s_tmem;

    const int tid = threadIdx.x;
    const int wid = tid >> 5;
    const int bm = blockIdx.y * 128;
    const int bn = blockIdx.x * 256;      // 2 tiles of 128 (ntiles==2)
    const uint32_t smem_base = smem_u32(smem);

    if (wid == 0) {
        TCGEN05_ALLOC(smem_u32(&s_tmem), 256);
        TCGEN05_RELINQ();
    }
    if (tid == 0) {
        MBARRIER_INIT(smem_u32(&s_mbar[0]), 1);
        MBARRIER_INIT(smem_u32(&s_mbar[1]), 1);
    }
    __syncthreads();
    const uint32_t tmem_d = s_tmem;
    const uint32_t mbar0 = smem_u32(&s_mbar[0]);
    const uint32_t mbar1 = smem_u32(&s_mbar[1]);

    const char* Abase  = (const char*)(A2 + (size_t)bm * KSP2);
    const char* B0base = (const char*)(B2 + (size_t)bn * KSP2);
    const char* B1base = B0base + (size_t)128 * ROWB;

    // one 16KB tile: 128 rows x 128B, SW128 swizzled
    auto load_tile = [&](const char* src, char* dst) {
        #pragma unroll
        for (int i = 0; i < 4; ++i) {
            int cidx = tid + i * 256;
            int row = cidx >> 3;
            int c16 = cidx & 7;
            uint4 v = *(const uint4*)(src + (size_t)row * ROWB + c16 * 16);
            *(uint4*)(dst + SWZ128(row * 128 + c16 * 16)) = v;
        }
    };
    auto load_step = [&](int kc, int s) {
        char* sb = smem + s * STAGE;
        const size_t ko = (size_t)kc * 128;    // byte offset of hi chunk
        load_tile(Abase  + ko,        sb);             // Ah
        load_tile(Abase  + 2048 + ko, sb + 16384);     // Al
        load_tile(B0base + ko,        sb + 32768);     // B0h
        load_tile(B0base + 2048 + ko, sb + 49152);     // B0l
        if (ntiles == 2) {
            load_tile(B1base + ko,        sb + 65536); // B1h
            load_tile(B1base + 2048 + ko, sb + 81920); // B1l
        }
    };

    load_step(0, 0);
    __syncthreads();

    int phase0 = 0, phase1 = 0;
    for (int kc = 0; kc < NSTEP; ++kc) {
        const int s = kc & 1;
        if (wid == 0) {
            FENCE_PROXY_ASYNC();
            if (elect_one_pred()) {
                const uint32_t base = smem_base + s * STAGE;
                const uint64_t dAh = MAKE_SMEM_DESC(base);
                const uint64_t dAl = MAKE_SMEM_DESC(base + 16384);
                for (int t = 0; t < ntiles; ++t) {
                    const uint64_t dBh = MAKE_SMEM_DESC(base + 32768 + t * 32768);
                    const uint64_t dBl = MAKE_SMEM_DESC(base + 49152 + t * 32768);
                    const uint32_t dt = tmem_d + t * 128;
                    #pragma unroll
                    for (int j = 0; j < 4; ++j)
                        TCGEN05_MMA_F16_SS(dt, dAh + j * 2, dBh + j * 2, MMA_IDESC,
                                           (kc > 0) || (j > 0));
                    #pragma unroll
                    for (int j = 0; j < 4; ++j)
                        TCGEN05_MMA_F16_SS(dt, dAh + j * 2, dBl + j * 2, MMA_IDESC, true);
                    #pragma unroll
                    for (int j = 0; j < 4; ++j)
                        TCGEN05_MMA_F16_SS(dt, dAl + j * 2, dBh + j * 2, MMA_IDESC, true);
                }
                TCGEN05_COMMIT(s == 0 ? mbar0 : mbar1);
            }
        }
        if (kc + 1 < NSTEP) {
            const int s2 = (kc + 1) & 1;
            if (kc >= 1) {
                if (s2 == 0) { MBARRIER_WAIT_PARITY(mbar0, phase0); phase0 ^= 1; }
                else         { MBARRIER_WAIT_PARITY(mbar1, phase1); phase1 ^= 1; }
            }
            load_step(kc + 1, s2);
        }
        __syncthreads();
    }
    // last step (kc=15) committed to mbar1
    MBARRIER_WAIT_PARITY(mbar1, phase1);
    TCGEN05_FENCE_AFTER();

    // epilogue: per D tile, warps 0-3 cols 0..63, warps 4-7 cols 64..127
    const int colbase = (wid >> 2) * 64;
    const int row = bm + (wid & 3) * 32 + (tid & 31);
    for (int t = 0; t < ntiles; ++t) {
        #pragma unroll
        for (int cb = 0; cb < 64; cb += 32) {
            uint32_t dr[32];
            TCGEN05_LD_X32(dr, tmem_d + t * 128 + colbase + cb);
            TCGEN05_WAIT_LD();
            TCGEN05_FENCE_BEFORE();
            #pragma unroll
            for (int c = 0; c < 32; c += 4) {
                const int col = bn + t * 128 + colbase + cb + c;
                float4 bs = *(const float4*)(bias + col);
                float4 o;
                o.x = scale * (__uint_as_float(dr[c + 0]) + bs.x);
                o.y = scale * (__uint_as_float(dr[c + 1]) + bs.y);
                o.z = scale * (__uint_as_float(dr[c + 2]) + bs.z);
                o.w = scale * (__uint_as_float(dr[c + 3]) + bs.w);
                if (RESID) {
                    float4 r = *(const float4*)(resid + (size_t)row * N + col);
                    o.x += r.x; o.y += r.y; o.z += r.z; o.w += r.w;
                }
                *(float4*)(out + (size_t)row * N + col) = o;
            }
        }
    }
    __syncthreads();
    if (tid == 0) { mbar_inval(mbar0); mbar_inval(mbar1); }
    __syncthreads();
    if (wid == 0) TCGEN05_DEALLOC(tmem_d, 256);
#else
    // Fallback for the compute_103 PTX pass (never run on sm_103a HW).
    const int tid = threadIdx.x;
    const int bm = blockIdx.y * 128;
    const int bn = blockIdx.x * 256;
    const int r0 = (tid >> 4) * 8;
    const int c0 = (tid & 15) * 8;
    for (int t = 0; t < ntiles; ++t)
    for (int i = 0; i < 8; ++i) {
        const int row = bm + r0 + i;
        const __nv_bfloat16* ar = A2 + (size_t)row * KSP2;
        for (int j = 0; j < 8; ++j) {
            const int col = bn + t * 128 + c0 + j;
            const __nv_bfloat16* br = B2 + (size_t)col * KSP2;
            float acc = 0.f;
            for (int k = 0; k < 1024; ++k) {
                float ah = __bfloat162float(ar[k]), al = __bfloat162float(ar[1024 + k]);
                float bh = __bfloat162float(br[k]), bl = __bfloat162float(br[1024 + k]);
                acc += ah * bh + ah * bl + al * bh;
            }
            float o = scale * (acc + bias[col]);
            if (RESID) o += resid[(size_t)row * N + col];
            out[(size_t)row * N + col] = o;
        }
    }
#endif
}

// ---------------- chunked scan, phase 1: per-chunk local scan ---------------
__global__ void __launch_bounds__(256) scan_phase1_kernel() {
    const int tid = threadIdx.x;
    const int gid = blockIdx.x * 16 + (tid >> 4);   // 0..NSUM-1
    const int e = tid & 15;
    const int j = gid >> 9;          // chunk
    const int c = gid & 511;         // chain
    const int b = c >> 6, h = c & 63;
    const int t0 = j * CHUNK;

    size_t off = ((size_t)b * LL + t0) * DD + h * HDIM + e;
    size_t offIF = ((size_t)b * LL + t0) * (2 * HH);

    float C[16];
    #pragma unroll
    for (int d = 0; d < 16; ++d) C[d] = 0.f;
    float n = 0.f, m = -1e30f, F = 0.f;

    for (int t = 0; t < CHUNK; ++t) {
        const float ke = g_k[off], ve = g_v[off];
        const float it = g_if[offIF + h];
        const float ft = g_if[offIF + HH + h];
        const float m_new = fmaxf(ft + m, it);
        const float fd = __expf(ft + m - m_new);
        const float id = __expf(it - m_new);
        m = m_new; F += ft;
        const float kid = id * ke;
        n = fd * n + kid;
        #pragma unroll
        for (int d = 0; d < 16; ++d) {
            const float vd = __shfl_sync(0xffffffffu, ve, d, 16);
            C[d] = fd * C[d] + vd * kid;
        }
        off += DD; offIF += 2 * HH;
    }
    float* cs = g_Cloc + (size_t)gid * 256;
    #pragma unroll
    for (int d = 0; d < 16; ++d) cs[d * 16 + e] = C[d];
    g_nloc[(size_t)gid * 16 + e] = n;
    if (e == 0) { g_mloc[gid] = m; g_Floc[gid] = F; }
}

// ---------------- phase 2: serial combine across chunks (per chain) ---------
__global__ void __launch_bounds__(256) scan_phase2_kernel() {
    const int tid = threadIdx.x;
    const int c = blockIdx.x * 16 + (tid >> 4);     // chain 0..511
    const int e = tid & 15;

    float C[16];
    #pragma unroll
    for (int d = 0; d < 16; ++d) C[d] = 0.f;
    float n = 0.f, m = 0.f;                          // reference init: zeros

    for (int j = 0; j < NCH; ++j) {
        const int sid = j * NCHAINS + c;
        float* ci = g_Cin + (size_t)sid * 256;
        #pragma unroll
        for (int d = 0; d < 16; ++d) ci[d * 16 + e] = C[d];
        g_nin[(size_t)sid * 16 + e] = n;
        if (e == 0) g_min[sid] = m;
        const float ml = g_mloc[sid];
        const float F  = g_Floc[sid];
        const float mo = fmaxf(m + F, ml);
        const float a  = __expf(m + F - mo);
        const float bb = __expf(ml - mo);
        const float* cl = g_Cloc + (size_t)sid * 256;
        #pragma unroll
        for (int d = 0; d < 16; ++d) C[d] = a * C[d] + bb * cl[d * 16 + e];
        n = a * n + bb * g_nloc[(size_t)sid * 16 + e];
        m = mo;
    }
}

// ---------------- phase 3: replay chunk from entering state, emit h ---------
__global__ void __launch_bounds__(256) scan_phase3_kernel() {
    const int tid = threadIdx.x;
    const int gid = blockIdx.x * 16 + (tid >> 4);
    const int e = tid & 15;
    const int j = gid >> 9;
    const int c = gid & 511;
    const int b = c >> 6, h = c & 63;
    const int t0 = j * CHUNK;

    size_t off = ((size_t)b * LL + t0) * DD + h * HDIM + e;
    size_t offIF = ((size_t)b * LL + t0) * (2 * HH);
    size_t h2off = ((size_t)b * LL + t0) * KSP2 + h * HDIM + e;

    const float* ci = g_Cin + (size_t)gid * 256;
    float C[16];
    #pragma unroll
    for (int d = 0; d < 16; ++d) C[d] = ci[d * 16 + e];
    float n = g_nin[(size_t)gid * 16 + e];
    float m = g_min[gid];

    for (int t = 0; t < CHUNK; ++t) {
        const float qe = g_q[off], ke = g_k[off], ve = g_v[off];
        const float it = g_if[offIF + h];
        const float ft = g_if[offIF + HH + h];
        const float m_new = fmaxf(ft + m, it);
        const float fd = __expf(ft + m - m_new);
        const float id = __expf(it - m_new);
        m = m_new;
        const float kid = id * ke;
        n = fd * n + kid;

        float cq = 0.f;
        #pragma unroll
        for (int d = 0; d < 16; ++d) {
            const float vd = __shfl_sync(0xffffffffu, ve, d, 16);
            const float qd = __shfl_sync(0xffffffffu, qe, d, 16);
            C[d] = fd * C[d] + vd * kid;
            cq = fmaf(C[d], qd, cq);
        }

        float nq = n * qe;
        #pragma unroll
        for (int o = 8; o; o >>= 1) nq += __shfl_xor_sync(0xffffffffu, nq, o, 16);
        const float denom = fmaxf(fabsf(nq), 1.0f);

        const float hval = cq / denom;
        __nv_bfloat16 hh, hl;
        split2(hval, hh, hl);
        g_h2[h2off] = hh;
        g_h2[h2off + 1024] = hl;

        off += DD; offIF += 2 * HH; h2off += KSP2;
    }
}

// ---------------- launch ----------------------------------------------------
extern "C" void kernel_launch(void* const* d_in, const int* in_sizes, int n_in,
                              void* d_out, int out_size) {
    (void)in_sizes; (void)n_in; (void)out_size;
    const float* x     = (const float*)d_in[0];
    const float* gamma = (const float*)d_in[1];
    const float* beta  = (const float*)d_in[2];
    const float* qw    = (const float*)d_in[3];
    const float* qb    = (const float*)d_in[4];
    const float* kw    = (const float*)d_in[5];
    const float* kb    = (const float*)d_in[6];
    const float* vw    = (const float*)d_in[7];
    const float* vb    = (const float*)d_in[8];
    const float* ow    = (const float*)d_in[9];
    const float* ob    = (const float*)d_in[10];
    const float* iw    = (const float*)d_in[11];
    const float* ib    = (const float*)d_in[12];
    const float* fw    = (const float*)d_in[13];
    const float* fb    = (const float*)d_in[14];
    float* out = (float*)d_out;

    __nv_bfloat16 *a2, *h2, *qw2, *kw2, *vw2, *ow2, *wif2;
    float *qp, *kp, *vp, *ifp, *wif, *bif;
    cudaGetSymbolAddress((void**)&a2,   g_a2);
    cudaGetSymbolAddress((void**)&h2,   g_h2);
    cudaGetSymbolAddress((void**)&qw2,  g_qw2);
    cudaGetSymbolAddress((void**)&kw2,  g_kw2);
    cudaGetSymbolAddress((void**)&vw2,  g_vw2);
    cudaGetSymbolAddress((void**)&ow2,  g_ow2);
    cudaGetSymbolAddress((void**)&wif2, g_wif2);
    cudaGetSymbolAddress((void**)&qp,   g_q);
    cudaGetSymbolAddress((void**)&kp,   g_k);
    cudaGetSymbolAddress((void**)&vp,   g_v);
    cudaGetSymbolAddress((void**)&ifp,  g_if);
    cudaGetSymbolAddress((void**)&wif,  g_wif);
    cudaGetSymbolAddress((void**)&bif,  g_bif);

    cudaFuncSetAttribute(mma_gemm_kernel<false>,
                         cudaFuncAttributeMaxDynamicSharedMemorySize, SMEM_SZ);
    cudaFuncSetAttribute(mma_gemm_kernel<true>,
                         cudaFuncAttributeMaxDynamicSharedMemorySize, SMEM_SZ);

    // 1. LN + split
    ln_split_kernel<<<MROWS, 256>>>(x, gamma, beta);
    // 2. weight prep
    combine_if_kernel<<<(2 * HH * DD + 255) / 256, 256>>>(iw, ib, fw, fb);
    split_kernel<<<(DD * 256 + 255) / 256, 256>>>(qw, qw2, DD);
    split_kernel<<<(DD * 256 + 255) / 256, 256>>>(kw, kw2, DD);
    split_kernel<<<(DD * 256 + 255) / 256, 256>>>(vw, vw2, DD);
    split_kernel<<<(DD * 256 + 255) / 256, 256>>>(ow, ow2, DD);
    split_kernel<<<(2 * HH * 256 + 255) / 256, 256>>>(wif, wif2, 2 * HH);

    // 3. projections on tcgen05 (2 N-tiles per CTA)
    dim3 gridBig(DD / 256, MROWS / 128);   // (4, 256)
    dim3 gridIF(1, MROWS / 128);           // (1, 256), 1 tile
    mma_gemm_kernel<false><<<gridBig, 256, SMEM_SZ>>>(a2, qw2, qb, nullptr, qp, DD, 1.0f, 2);
    mma_gemm_kernel<false><<<gridBig, 256, SMEM_SZ>>>(a2, kw2, kb, nullptr, kp, DD, 0.25f, 2);
    mma_gemm_kernel<false><<<gridBig, 256, SMEM_SZ>>>(a2, vw2, vb, nullptr, vp, DD, 1.0f, 2);
    mma_gemm_kernel<false><<<gridIF, 256, SMEM_SZ>>>(a2, wif2, bif, nullptr, ifp, 2 * HH, 1.0f, 1);

    // 4. chunked parallel scan
    scan_phase1_kernel<<<NSUM / 16, 256>>>();
    scan_phase2_kernel<<<NCHAINS / 16, 256>>>();
    scan_phase3_kernel<<<NSUM / 16, 256>>>();

    // 5. output projection + residual
    mma_gemm_kernel<true><<<gridBig, 256, SMEM_SZ>>>(h2, ow2, ob, x, out, DD, 1.0f, 2);
}